// round 4
// baseline (speedup 1.0000x reference)
#include <cuda_runtime.h>

typedef unsigned long long u64;

#define NLAY    3
#define TSTEPS  128
#define MTILE   128
#define NTHREADS 512

// Reordered weights (filled by prep_kernel every launch):
//  g_embT[(k*16 + cg)*4 + j]             = emb_w[(cg*4+j)*64 + k]
//  g_wT[((l*64+k)*16 + cg)*24 + g*4 + j] = g<3 ? w_ih[l][g*64 + cg*4+j][k]
//                                               : w_hh[l][(g-3)*64 + cg*4+j][k]
// so each thread's per-k weight slice (6 gates x 4 cols) is 96 contiguous bytes,
// and a warp's slice (4 cgroups) is 384 contiguous bytes = 3 cache lines.
__device__ __align__(16) float g_embT[64 * 64];
__device__ __align__(16) float g_wT[NLAY * 64 * 16 * 24];

__global__ void prep_kernel(const float* __restrict__ emb_w,
                            const float* __restrict__ w_ih,
                            const float* __restrict__ w_hh)
{
    int t0 = blockIdx.x * blockDim.x + threadIdx.x;
    int stride = gridDim.x * blockDim.x;
    for (int i = t0; i < 64 * 64; i += stride) {
        // i = (k*16 + cg)*4 + j
        int j = i & 3, kcg = i >> 2;
        int cg = kcg & 15, k = kcg >> 4;
        g_embT[i] = emb_w[(cg * 4 + j) * 64 + k];
    }
    for (int i = t0; i < NLAY * 64 * 16 * 24; i += stride) {
        // i = ((l*64+k)*16 + cg)*24 + g*4 + j
        int j = i % 4;
        int g = (i / 4) % 6;
        int cg = (i / 24) % 16;
        int k = (i / (24 * 16)) % 64;
        int l = i / (24 * 16 * 64);
        int c = cg * 4 + j;
        float v = (g < 3) ? w_ih[(l * 192 + g * 64 + c) * 64 + k]
                          : w_hh[(l * 192 + (g - 3) * 64 + c) * 64 + k];
        g_wT[i] = v;
    }
}

// ---- packed f32x2 helpers ----
__device__ __forceinline__ u64 dup2(float v) {
    u64 d; asm("mov.b64 %0,{%1,%1};" : "=l"(d) : "f"(v)); return d;
}
__device__ __forceinline__ u64 pk2(float a, float b) {
    u64 d; asm("mov.b64 %0,{%1,%2};" : "=l"(d) : "f"(a), "f"(b)); return d;
}
__device__ __forceinline__ void up2(u64 v, float& a, float& b) {
    asm("mov.b64 {%0,%1},%2;" : "=f"(a), "=f"(b) : "l"(v));
}
__device__ __forceinline__ u64 f2fma(u64 a, u64 b, u64 c) {
    u64 d; asm("fma.rn.f32x2 %0,%1,%2,%3;" : "=l"(d) : "l"(a), "l"(b), "l"(c));
    return d;
}
__device__ __forceinline__ void ldg2(const float* p, u64& a, u64& b) {
    asm("ld.global.nc.v2.b64 {%0,%1},[%2];" : "=l"(a), "=l"(b) : "l"(p));
}
__device__ __forceinline__ float sigmf(float x) {
    return __fdividef(1.f, 1.f + __expf(-x));
}
__device__ __forceinline__ float tanhfast(float x) {
    return 1.f - __fdividef(2.f, __expf(2.f * x) + 1.f);
}

// Persistent per-CTA GRU decoder: 128 rows/CTA, all 128 steps.
// SMEM: sX, sH0, sH1, sH2 each [64 feat][128 rows] (feature-major).
// Thread map: warp covers 4 col-groups x 8 row-groups (16 cols x 32 rows)
//   cg = (warp&3)*4 + (lane&3)   -> c0 = cg*4
//   rg = (warp>>2)*8 + (lane>>2) -> r0 = rg*4
extern "C" __global__ void __launch_bounds__(NTHREADS, 1)
gru_kernel(const float* __restrict__ enc,
           const float* __restrict__ emb_b,
           const float* __restrict__ b_ih,
           const float* __restrict__ b_hh,
           const float* __restrict__ out_w,
           const float* __restrict__ out_b,
           float* __restrict__ out)
{
    extern __shared__ float sm[];      // 4 * 8192 floats = 128 KB
    const int tid  = threadIdx.x;
    const int lane = tid & 31;
    const int warp = tid >> 5;
    const int row0 = blockIdx.x * MTILE;
    const int cg = (warp & 3) * 4 + (lane & 3);
    const int c0 = cg * 4;
    const int r0 = ((warp >> 2) * 8 + (lane >> 2)) * 4;

    // init all three hidden states to enc (transposed)
    for (int i = tid; i < 64 * MTILE; i += NTHREADS) {
        int m = i >> 6, e = i & 63;                 // coalesced enc read
        float v = enc[(size_t)(row0 + m) * 64 + e];
        sm[8192  + e * 128 + m] = v;
        sm[16384 + e * 128 + m] = v;
        sm[24576 + e * 128 + m] = v;
    }
    __syncthreads();

    // embedding bias (constant over t)
    const float4 ebv = *(const float4*)(emb_b + c0);
    const u64 embB0 = pk2(ebv.x, ebv.y);
    const u64 embB1 = pk2(ebv.z, ebv.w);
    const int om = tid & 127;          // output-layer mapping (tid<256)
    const int oj = tid >> 7;

    for (int t = 0; t < TSTEPS; t++) {
        float* sH2 = sm + 24576;

        // ========= embedding: sX = sH2 @ emb_w^T + emb_b =========
        {
            u64 a0[4], a1[4];
            #pragma unroll
            for (int r = 0; r < 4; r++) { a0[r] = embB0; a1[r] = embB1; }
            #pragma unroll 4
            for (int k = 0; k < 64; k++) {
                float4 x4 = *(const float4*)(sH2 + k * 128 + r0);
                u64 w0, w1; ldg2(g_embT + (k * 16 + cg) * 4, w0, w1);
                float xs[4] = {x4.x, x4.y, x4.z, x4.w};
                #pragma unroll
                for (int r = 0; r < 4; r++) {
                    u64 xd = dup2(xs[r]);
                    a0[r] = f2fma(xd, w0, a0[r]);
                    a1[r] = f2fma(xd, w1, a1[r]);
                }
            }
            float v[4][4];
            #pragma unroll
            for (int r = 0; r < 4; r++) {
                up2(a0[r], v[r][0], v[r][1]);
                up2(a1[r], v[r][2], v[r][3]);
            }
            #pragma unroll
            for (int cc = 0; cc < 4; cc++)
                *(float4*)(sm + (c0 + cc) * 128 + r0) =
                    make_float4(v[0][cc], v[1][cc], v[2][cc], v[3][cc]);
        }
        __syncthreads();

        // ========= 3 GRU layers =========
        #pragma unroll 1
        for (int l = 0; l < NLAY; l++) {
            const float* Xb = sm + l * 8192;        // l=0 -> sX
            float*       Hb = sm + (l + 1) * 8192;  // sH_l

            u64 aR[4][2], aZ[4][2], aN[4][2], aM[4][2];
            {
                const float* bi = b_ih + l * 192 + c0;
                const float* bh = b_hh + l * 192 + c0;
                float4 bir = *(const float4*)bi,         bhr = *(const float4*)bh;
                float4 biz = *(const float4*)(bi + 64),  bhz = *(const float4*)(bh + 64);
                float4 bin = *(const float4*)(bi + 128), bhn = *(const float4*)(bh + 128);
                u64 iR0 = pk2(bir.x + bhr.x, bir.y + bhr.y), iR1 = pk2(bir.z + bhr.z, bir.w + bhr.w);
                u64 iZ0 = pk2(biz.x + bhz.x, biz.y + bhz.y), iZ1 = pk2(biz.z + bhz.z, biz.w + bhz.w);
                u64 iN0 = pk2(bin.x, bin.y), iN1 = pk2(bin.z, bin.w);
                u64 iM0 = pk2(bhn.x, bhn.y), iM1 = pk2(bhn.z, bhn.w);
                #pragma unroll
                for (int r = 0; r < 4; r++) {
                    aR[r][0] = iR0; aR[r][1] = iR1;
                    aZ[r][0] = iZ0; aZ[r][1] = iZ1;
                    aN[r][0] = iN0; aN[r][1] = iN1;
                    aM[r][0] = iM0; aM[r][1] = iM1;
                }
            }

            // per-thread weight slice: 96 contiguous bytes per k
            const float* wbase = g_wT + ((size_t)(l * 64) * 16 + cg) * 24;
            #pragma unroll 2
            for (int k = 0; k < 64; k++) {
                float4 x4 = *(const float4*)(Xb + k * 128 + r0);
                float4 h4 = *(const float4*)(Hb + k * 128 + r0);
                const float* wr = wbase + k * (16 * 24);
                u64 wir0, wir1, wiz0, wiz1, win0, win1;
                u64 whr0, whr1, whz0, whz1, whn0, whn1;
                ldg2(wr,      wir0, wir1);
                ldg2(wr + 4,  wiz0, wiz1);
                ldg2(wr + 8,  win0, win1);
                ldg2(wr + 12, whr0, whr1);
                ldg2(wr + 16, whz0, whz1);
                ldg2(wr + 20, whn0, whn1);
                float xs[4] = {x4.x, x4.y, x4.z, x4.w};
                float hs[4] = {h4.x, h4.y, h4.z, h4.w};
                #pragma unroll
                for (int r = 0; r < 4; r++) {
                    u64 xd = dup2(xs[r]), hd = dup2(hs[r]);
                    aR[r][0] = f2fma(xd, wir0, aR[r][0]);
                    aR[r][0] = f2fma(hd, whr0, aR[r][0]);
                    aR[r][1] = f2fma(xd, wir1, aR[r][1]);
                    aR[r][1] = f2fma(hd, whr1, aR[r][1]);
                    aZ[r][0] = f2fma(xd, wiz0, aZ[r][0]);
                    aZ[r][0] = f2fma(hd, whz0, aZ[r][0]);
                    aZ[r][1] = f2fma(xd, wiz1, aZ[r][1]);
                    aZ[r][1] = f2fma(hd, whz1, aZ[r][1]);
                    aN[r][0] = f2fma(xd, win0, aN[r][0]);
                    aN[r][1] = f2fma(xd, win1, aN[r][1]);
                    aM[r][0] = f2fma(hd, whn0, aM[r][0]);
                    aM[r][1] = f2fma(hd, whn1, aM[r][1]);
                }
            }
            __syncthreads();   // all reads of Hb done before overwrite

            #pragma unroll
            for (int cc = 0; cc < 4; cc++) {
                float4 ho = *(const float4*)(Hb + (c0 + cc) * 128 + r0);
                float hos[4] = {ho.x, ho.y, ho.z, ho.w};
                float res[4];
                #pragma unroll
                for (int r = 0; r < 4; r++) {
                    float p0, p1, R, Z, N, M;
                    up2(aR[r][cc >> 1], p0, p1); R = (cc & 1) ? p1 : p0;
                    up2(aZ[r][cc >> 1], p0, p1); Z = (cc & 1) ? p1 : p0;
                    up2(aN[r][cc >> 1], p0, p1); N = (cc & 1) ? p1 : p0;
                    up2(aM[r][cc >> 1], p0, p1); M = (cc & 1) ? p1 : p0;
                    float rg = sigmf(R);
                    float zg = sigmf(Z);
                    float ng = tanhfast(fmaf(rg, M, N));
                    res[r] = fmaf(zg, hos[r] - ng, ng);
                }
                *(float4*)(Hb + (c0 + cc) * 128 + r0) =
                    make_float4(res[0], res[1], res[2], res[3]);
            }
            __syncthreads();
        }

        // ========= output: out[:, t, :] = sH2 @ out_w^T + out_b =========
        if (tid < 256) {
            float a = out_b[oj];
            const float* ow = out_w + oj * 64;
            #pragma unroll 8
            for (int e = 0; e < 64; e++)
                a = fmaf(sH2[e * 128 + om], ow[e], a);
            out[(size_t)(row0 + om) * (TSTEPS * 2) + t * 2 + oj] = a;
        }
        // no sync needed: next emb only READS sH2 (as does the output pass)
    }
}

extern "C" void kernel_launch(void* const* d_in, const int* in_sizes, int n_in,
                              void* d_out, int out_size)
{
    const float* enc   = (const float*)d_in[0];
    const float* emb_w = (const float*)d_in[1];
    const float* emb_b = (const float*)d_in[2];
    const float* w_ih  = (const float*)d_in[3];
    const float* w_hh  = (const float*)d_in[4];
    const float* b_ih  = (const float*)d_in[5];
    const float* b_hh  = (const float*)d_in[6];
    const float* out_w = (const float*)d_in[7];
    const float* out_b = (const float*)d_in[8];

    cudaFuncSetAttribute(gru_kernel,
                         cudaFuncAttributeMaxDynamicSharedMemorySize,
                         131072);

    prep_kernel<<<64, 256>>>(emb_w, w_ih, w_hh);
    gru_kernel<<<128, NTHREADS, 131072>>>(enc, emb_b, b_ih, b_hh,
                                          out_w, out_b, (float*)d_out);
}

// round 5
// speedup vs baseline: 1.1941x; 1.1941x over previous
#include <cuda_runtime.h>

typedef unsigned long long u64;

#define NLAY    3
#define TSTEPS  128
#define MTILE   32
#define NTHREADS 128

// Reordered weights (filled by prep_kernel every launch):
//  g_embT[(k*16 + cg)*4 + j]             = emb_w[(cg*4+j)*64 + k]
//  g_wT[((l*64+k)*16 + cg)*24 + g*4 + j] = g<3 ? w_ih[l][g*64 + cg*4+j][k]
//                                               : w_hh[l][(g-3)*64 + cg*4+j][k]
__device__ __align__(16) float g_embT[64 * 64];
__device__ __align__(16) float g_wT[NLAY * 64 * 16 * 24];

__global__ void prep_kernel(const float* __restrict__ emb_w,
                            const float* __restrict__ w_ih,
                            const float* __restrict__ w_hh)
{
    int t0 = blockIdx.x * blockDim.x + threadIdx.x;
    int stride = gridDim.x * blockDim.x;
    for (int i = t0; i < 64 * 64; i += stride) {
        int j = i & 3, kcg = i >> 2;
        int cg = kcg & 15, k = kcg >> 4;
        g_embT[i] = emb_w[(cg * 4 + j) * 64 + k];
    }
    for (int i = t0; i < NLAY * 64 * 16 * 24; i += stride) {
        int j = i % 4;
        int g = (i / 4) % 6;
        int cg = (i / 24) % 16;
        int k = (i / (24 * 16)) % 64;
        int l = i / (24 * 16 * 64);
        int c = cg * 4 + j;
        float v = (g < 3) ? w_ih[(l * 192 + g * 64 + c) * 64 + k]
                          : w_hh[(l * 192 + (g - 3) * 64 + c) * 64 + k];
        g_wT[i] = v;
    }
}

// ---- packed f32x2 helpers ----
__device__ __forceinline__ u64 dup2(float v) {
    u64 d; asm("mov.b64 %0,{%1,%1};" : "=l"(d) : "f"(v)); return d;
}
__device__ __forceinline__ u64 pk2(float a, float b) {
    u64 d; asm("mov.b64 %0,{%1,%2};" : "=l"(d) : "f"(a), "f"(b)); return d;
}
__device__ __forceinline__ void up2(u64 v, float& a, float& b) {
    asm("mov.b64 {%0,%1},%2;" : "=f"(a), "=f"(b) : "l"(v));
}
__device__ __forceinline__ u64 f2fma(u64 a, u64 b, u64 c) {
    u64 d; asm("fma.rn.f32x2 %0,%1,%2,%3;" : "=l"(d) : "l"(a), "l"(b), "l"(c));
    return d;
}
__device__ __forceinline__ void ldg2(const float* p, u64& a, u64& b) {
    asm("ld.global.nc.v2.b64 {%0,%1},[%2];" : "=l"(a), "=l"(b) : "l"(p));
}
__device__ __forceinline__ float sigmf(float x) {
    return __fdividef(1.f, 1.f + __expf(-x));
}
__device__ __forceinline__ float tanhfast(float x) {
    return 1.f - __fdividef(2.f, __expf(2.f * x) + 1.f);
}

// Persistent per-CTA GRU decoder: 32 rows/CTA, all 128 steps.
// 4 CTAs/SM for inter-CTA latency hiding.
// SMEM: sX, sH0, sH1, sH2 each [64 feat][32 rows] (feature-major), 32 KB total.
// Thread map (4 warps): cg = warp*4 + (lane&3); rg = lane>>2 (8 groups of 4 rows)
extern "C" __global__ void __launch_bounds__(NTHREADS, 4)
gru_kernel(const float* __restrict__ enc,
           const float* __restrict__ emb_b,
           const float* __restrict__ b_ih,
           const float* __restrict__ b_hh,
           const float* __restrict__ out_w,
           const float* __restrict__ out_b,
           float* __restrict__ out)
{
    extern __shared__ float sm[];      // 4 * 2048 floats = 32 KB
    const int tid  = threadIdx.x;
    const int lane = tid & 31;
    const int warp = tid >> 5;
    const int row0 = blockIdx.x * MTILE;
    const int cg = warp * 4 + (lane & 3);
    const int c0 = cg * 4;
    const int r0 = (lane >> 2) * 4;

    // init all three hidden states to enc (transposed)
    for (int i = tid; i < 64 * MTILE; i += NTHREADS) {
        int m = i >> 6, e = i & 63;                 // coalesced enc read
        float v = enc[(size_t)(row0 + m) * 64 + e];
        sm[2048 + e * MTILE + m] = v;
        sm[4096 + e * MTILE + m] = v;
        sm[6144 + e * MTILE + m] = v;
    }
    __syncthreads();

    // embedding bias (constant over t)
    const float4 ebv = *(const float4*)(emb_b + c0);
    const u64 embB0 = pk2(ebv.x, ebv.y);
    const u64 embB1 = pk2(ebv.z, ebv.w);
    const int om = tid & 31;           // output-layer mapping (tid<64)
    const int oj = tid >> 5;

    for (int t = 0; t < TSTEPS; t++) {
        float* sH2 = sm + 6144;

        // ========= embedding: sX = sH2 @ emb_w^T + emb_b =========
        {
            u64 a0[4], a1[4];
            #pragma unroll
            for (int r = 0; r < 4; r++) { a0[r] = embB0; a1[r] = embB1; }
            #pragma unroll 4
            for (int k = 0; k < 64; k++) {
                float4 x4 = *(const float4*)(sH2 + k * MTILE + r0);
                u64 w0, w1; ldg2(g_embT + (k * 16 + cg) * 4, w0, w1);
                float xs[4] = {x4.x, x4.y, x4.z, x4.w};
                #pragma unroll
                for (int r = 0; r < 4; r++) {
                    u64 xd = dup2(xs[r]);
                    a0[r] = f2fma(xd, w0, a0[r]);
                    a1[r] = f2fma(xd, w1, a1[r]);
                }
            }
            float v[4][4];
            #pragma unroll
            for (int r = 0; r < 4; r++) {
                up2(a0[r], v[r][0], v[r][1]);
                up2(a1[r], v[r][2], v[r][3]);
            }
            #pragma unroll
            for (int cc = 0; cc < 4; cc++)
                *(float4*)(sm + (c0 + cc) * MTILE + r0) =
                    make_float4(v[0][cc], v[1][cc], v[2][cc], v[3][cc]);
        }
        __syncthreads();

        // ========= 3 GRU layers =========
        #pragma unroll 1
        for (int l = 0; l < NLAY; l++) {
            const float* Xb = sm + l * 2048;        // l=0 -> sX
            float*       Hb = sm + (l + 1) * 2048;  // sH_l

            u64 aR[4][2], aZ[4][2], aN[4][2], aM[4][2];
            {
                const float* bi = b_ih + l * 192 + c0;
                const float* bh = b_hh + l * 192 + c0;
                float4 bir = *(const float4*)bi,         bhr = *(const float4*)bh;
                float4 biz = *(const float4*)(bi + 64),  bhz = *(const float4*)(bh + 64);
                float4 bin = *(const float4*)(bi + 128), bhn = *(const float4*)(bh + 128);
                u64 iR0 = pk2(bir.x + bhr.x, bir.y + bhr.y), iR1 = pk2(bir.z + bhr.z, bir.w + bhr.w);
                u64 iZ0 = pk2(biz.x + bhz.x, biz.y + bhz.y), iZ1 = pk2(biz.z + bhz.z, biz.w + bhz.w);
                u64 iN0 = pk2(bin.x, bin.y), iN1 = pk2(bin.z, bin.w);
                u64 iM0 = pk2(bhn.x, bhn.y), iM1 = pk2(bhn.z, bhn.w);
                #pragma unroll
                for (int r = 0; r < 4; r++) {
                    aR[r][0] = iR0; aR[r][1] = iR1;
                    aZ[r][0] = iZ0; aZ[r][1] = iZ1;
                    aN[r][0] = iN0; aN[r][1] = iN1;
                    aM[r][0] = iM0; aM[r][1] = iM1;
                }
            }

            // per-thread weight slice: 96 contiguous bytes per k
            const float* wbase = g_wT + ((size_t)(l * 64) * 16 + cg) * 24;
            #pragma unroll 2
            for (int k = 0; k < 64; k++) {
                float4 x4 = *(const float4*)(Xb + k * MTILE + r0);
                float4 h4 = *(const float4*)(Hb + k * MTILE + r0);
                const float* wr = wbase + k * (16 * 24);
                u64 wir0, wir1, wiz0, wiz1, win0, win1;
                u64 whr0, whr1, whz0, whz1, whn0, whn1;
                ldg2(wr,      wir0, wir1);
                ldg2(wr + 4,  wiz0, wiz1);
                ldg2(wr + 8,  win0, win1);
                ldg2(wr + 12, whr0, whr1);
                ldg2(wr + 16, whz0, whz1);
                ldg2(wr + 20, whn0, whn1);
                float xs[4] = {x4.x, x4.y, x4.z, x4.w};
                float hs[4] = {h4.x, h4.y, h4.z, h4.w};
                #pragma unroll
                for (int r = 0; r < 4; r++) {
                    u64 xd = dup2(xs[r]), hd = dup2(hs[r]);
                    aR[r][0] = f2fma(xd, wir0, aR[r][0]);
                    aR[r][0] = f2fma(hd, whr0, aR[r][0]);
                    aR[r][1] = f2fma(xd, wir1, aR[r][1]);
                    aR[r][1] = f2fma(hd, whr1, aR[r][1]);
                    aZ[r][0] = f2fma(xd, wiz0, aZ[r][0]);
                    aZ[r][0] = f2fma(hd, whz0, aZ[r][0]);
                    aZ[r][1] = f2fma(xd, wiz1, aZ[r][1]);
                    aZ[r][1] = f2fma(hd, whz1, aZ[r][1]);
                    aN[r][0] = f2fma(xd, win0, aN[r][0]);
                    aN[r][1] = f2fma(xd, win1, aN[r][1]);
                    aM[r][0] = f2fma(hd, whn0, aM[r][0]);
                    aM[r][1] = f2fma(hd, whn1, aM[r][1]);
                }
            }
            __syncthreads();   // all reads of Hb done before overwrite

            #pragma unroll
            for (int cc = 0; cc < 4; cc++) {
                float4 ho = *(const float4*)(Hb + (c0 + cc) * MTILE + r0);
                float hos[4] = {ho.x, ho.y, ho.z, ho.w};
                float res[4];
                #pragma unroll
                for (int r = 0; r < 4; r++) {
                    float p0, p1, R, Z, N, M;
                    up2(aR[r][cc >> 1], p0, p1); R = (cc & 1) ? p1 : p0;
                    up2(aZ[r][cc >> 1], p0, p1); Z = (cc & 1) ? p1 : p0;
                    up2(aN[r][cc >> 1], p0, p1); N = (cc & 1) ? p1 : p0;
                    up2(aM[r][cc >> 1], p0, p1); M = (cc & 1) ? p1 : p0;
                    float rg = sigmf(R);
                    float zg = sigmf(Z);
                    float ng = tanhfast(fmaf(rg, M, N));
                    res[r] = fmaf(zg, hos[r] - ng, ng);
                }
                *(float4*)(Hb + (c0 + cc) * MTILE + r0) =
                    make_float4(res[0], res[1], res[2], res[3]);
            }
            __syncthreads();
        }

        // ========= output: out[:, t, :] = sH2 @ out_w^T + out_b =========
        if (tid < 64) {
            float a = out_b[oj];
            const float* ow = out_w + oj * 64;
            #pragma unroll 8
            for (int e = 0; e < 64; e++)
                a = fmaf(sH2[e * MTILE + om], ow[e], a);
            out[(size_t)(row0 + om) * (TSTEPS * 2) + t * 2 + oj] = a;
        }
        // no sync needed: next emb only READS sH2 (as does the output pass)
    }
}

extern "C" void kernel_launch(void* const* d_in, const int* in_sizes, int n_in,
                              void* d_out, int out_size)
{
    const float* enc   = (const float*)d_in[0];
    const float* emb_w = (const float*)d_in[1];
    const float* emb_b = (const float*)d_in[2];
    const float* w_ih  = (const float*)d_in[3];
    const float* w_hh  = (const float*)d_in[4];
    const float* b_ih  = (const float*)d_in[5];
    const float* b_hh  = (const float*)d_in[6];
    const float* out_w = (const float*)d_in[7];
    const float* out_b = (const float*)d_in[8];

    prep_kernel<<<64, 256>>>(emb_w, w_ih, w_hh);
    gru_kernel<<<512, NTHREADS, 32768>>>(enc, emb_b, b_ih, b_hh,
                                         out_w, out_b, (float*)d_out);
}

// round 7
// speedup vs baseline: 2.2754x; 1.9055x over previous
#include <cuda_runtime.h>
#include <cuda_bf16.h>

typedef unsigned long long u64;
typedef unsigned int u32;

#define TSTEPS 128
#define NTH    256

// =============== prepped weights (global scratch) ===============
// B-fragment-linear weights for mma.m16n8k16 (B frag: b0: k=2t+{0,1}, n=g; b1: k+8):
// g_wfrag layout [l][side][part][kt(4)][nt(24)][lane(32)][reg(2)] u32
//   side0=w_ih side1=w_hh ; part0=hi part1=lo(residual)
__device__ __align__(16) u32 g_wfrag[3 * 2 * 2 * 4 * 24 * 32 * 2];   // 73728 u32
// emb: [part][kt(4)][nt(8)][lane][reg] u32
__device__ __align__(16) u32 g_efrag[2 * 4 * 8 * 32 * 2];            // 4096 u32
// combined biases: per layer [0:64)=bir+bhr [64:128)=biz+bhz [128:192)=bin [192:256)=bhn
__device__ __align__(16) float g_bias[3 * 256];

__device__ __forceinline__ u32 packbf(float a, float b) {
    return (u32)__bfloat16_as_ushort(__float2bfloat16(a)) |
           ((u32)__bfloat16_as_ushort(__float2bfloat16(b)) << 16);
}
__device__ __forceinline__ float blo(u32 v) {
    return __bfloat162float(__ushort_as_bfloat16((unsigned short)(v & 0xFFFF)));
}
__device__ __forceinline__ float bhi(u32 v) {
    return __bfloat162float(__ushort_as_bfloat16((unsigned short)(v >> 16)));
}

__global__ void prep_kernel(const float* __restrict__ emb_w,
                            const float* __restrict__ w_ih,
                            const float* __restrict__ w_hh,
                            const float* __restrict__ b_ih,
                            const float* __restrict__ b_hh)
{
    int i0 = blockIdx.x * blockDim.x + threadIdx.x;
    int st = gridDim.x * blockDim.x;
    // layer weights
    for (int i = i0; i < 73728; i += st) {
        int reg  = i & 1;
        int lane = (i >> 1) & 31;
        int nt   = (i >> 6) % 24;
        int kt   = (i / 1536) % 4;
        int part = (i / 6144) % 2;
        int side = (i / 12288) % 2;
        int l    = i / 24576;
        int g = lane >> 2, tg = lane & 3;
        int n = nt * 8 + g;
        int k0 = kt * 16 + tg * 2 + reg * 8;
        const float* W = side ? w_hh : w_ih;
        float w0 = W[(l * 192 + n) * 64 + k0];
        float w1 = W[(l * 192 + n) * 64 + k0 + 1];
        if (part == 0) {
            g_wfrag[i] = packbf(w0, w1);
        } else {
            float r0 = w0 - __bfloat162float(__float2bfloat16(w0));
            float r1 = w1 - __bfloat162float(__float2bfloat16(w1));
            g_wfrag[i] = packbf(r0, r1);
        }
    }
    // emb weights
    for (int i = i0; i < 4096; i += st) {
        int reg  = i & 1;
        int lane = (i >> 1) & 31;
        int nt   = (i >> 6) & 7;
        int kt   = (i >> 9) & 3;
        int part = i >> 11;
        int g = lane >> 2, tg = lane & 3;
        int n = nt * 8 + g;
        int k0 = kt * 16 + tg * 2 + reg * 8;
        float w0 = emb_w[n * 64 + k0], w1 = emb_w[n * 64 + k0 + 1];
        if (part == 0) {
            g_efrag[i] = packbf(w0, w1);
        } else {
            float r0 = w0 - __bfloat162float(__float2bfloat16(w0));
            float r1 = w1 - __bfloat162float(__float2bfloat16(w1));
            g_efrag[i] = packbf(r0, r1);
        }
    }
    // biases
    for (int i = i0; i < 3 * 64; i += st) {
        int l = i >> 6, c = i & 63;
        g_bias[l * 256 + c]       = b_ih[l * 192 + c]      + b_hh[l * 192 + c];
        g_bias[l * 256 + 64 + c]  = b_ih[l * 192 + 64 + c] + b_hh[l * 192 + 64 + c];
        g_bias[l * 256 + 128 + c] = b_ih[l * 192 + 128 + c];
        g_bias[l * 256 + 192 + c] = b_hh[l * 192 + 128 + c];
    }
}

// =============== device helpers ===============
__device__ __forceinline__ u32 smem_u32(const void* p) {
    u32 a;
    asm("{ .reg .u64 t; cvta.to.shared.u64 t, %1; cvt.u32.u64 %0, t; }" : "=r"(a) : "l"(p));
    return a;
}
__device__ __forceinline__ void mma16816(float* d, const u32* a, u32 b0, u32 b1) {
    asm volatile(
        "mma.sync.aligned.m16n8k16.row.col.f32.bf16.bf16.f32 "
        "{%0,%1,%2,%3},{%4,%5,%6,%7},{%8,%9},{%0,%1,%2,%3};"
        : "+f"(d[0]), "+f"(d[1]), "+f"(d[2]), "+f"(d[3])
        : "r"(a[0]), "r"(a[1]), "r"(a[2]), "r"(a[3]), "r"(b0), "r"(b1));
}
__device__ __forceinline__ void lds128(u32* r, u32 a) {
    asm volatile("ld.shared.v4.u32 {%0,%1,%2,%3},[%4];"
                 : "=r"(r[0]), "=r"(r[1]), "=r"(r[2]), "=r"(r[3]) : "r"(a));
}
__device__ __forceinline__ void lds64(u32& x, u32& y, u32 a) {
    asm volatile("ld.shared.v2.u32 {%0,%1},[%2];" : "=r"(x), "=r"(y) : "r"(a));
}
__device__ __forceinline__ void sts64(u32 a, u32 x, u32 y) {
    asm volatile("st.shared.v2.u32 [%0],{%1,%2};" :: "r"(a), "r"(x), "r"(y));
}
__device__ __forceinline__ void cpasync16(u32 s, const void* g) {
    asm volatile("cp.async.ca.shared.global [%0],[%1],16;" :: "r"(s), "l"(g));
}
__device__ __forceinline__ void cpcommit() { asm volatile("cp.async.commit_group;"); }
__device__ __forceinline__ void cpwaitall() { asm volatile("cp.async.wait_group 0;"); }
__device__ __forceinline__ float sigmf(float x) { return __fdividef(1.f, 1.f + __expf(-x)); }
__device__ __forceinline__ float tanhfast(float x) { return 1.f - __fdividef(2.f, __expf(2.f * x) + 1.f); }

// SMEM (bytes): states 4 x (2 parts x 16384) = 131072 ; wbuf 2 x 24576 = 49152
#define SO_W   131072
#define SMEMSZ (SO_W + 49152)

// A-frag-linear state addressing: state s, part p, mtile mt, ktile kt, lane:
//   byte = s*32768 + p*16384 + mt*2048 + kt*512 + lane*16  (4 u32 regs a0..a3)
// a0=(row g,   k=2t,2t+1)  a1=(row g+8, same k)  a2=(row g, k+8,+9)  a3=(row g+8, k+8,+9)

extern "C" __global__ void __launch_bounds__(NTH, 1)
gru_mma_kernel(const float* __restrict__ enc,
               const float* __restrict__ emb_b,
               const float* __restrict__ out_w,
               const float* __restrict__ out_b,
               float* __restrict__ out)
{
    extern __shared__ char smc[];
    const u32 sb  = smem_u32(smc);
    const int tid  = threadIdx.x;
    const int lane = tid & 31;
    const int warp = tid >> 5;            // = mtile, 8 warps x 16 rows
    const int g    = lane >> 2;
    const int tg   = lane & 3;
    const int row0 = blockIdx.x * 128;

    // ---- init H0/H1/H2 (states 1..3) frag-linear from enc ----
    for (int i = tid; i < 128 * 32; i += NTH) {
        int m = i >> 5, kp = i & 31;      // row m, k-pair kp
        int k = kp * 2;
        float v0 = enc[(size_t)(row0 + m) * 64 + k];
        float v1 = enc[(size_t)(row0 + m) * 64 + k + 1];
        u32 hi = packbf(v0, v1);
        u32 lo = packbf(v0 - blo(hi), v1 - bhi(hi));
        int kt = k >> 4, kin = k & 15;
        int gg = m & 15;
        int reg = ((kin >= 8) ? 2 : 0) + ((gg >= 8) ? 1 : 0);
        int ln = (gg & 7) * 4 + ((kin & 7) >> 1);
        u32 off = (u32)((m >> 4) * 2048 + kt * 512 + ln * 16 + reg * 4);
        #pragma unroll
        for (int s = 1; s <= 3; s++) {
            *(u32*)(smc + s * 32768 + off)         = hi;
            *(u32*)(smc + s * 32768 + 16384 + off) = lo;
        }
    }

    // phase sources: 0,1 = emb hi/lo ; 2+l*4+p = layer l part p
    const char* srcs[14]; int szs[14];
    srcs[0] = (const char*)g_efrag;        szs[0] = 8192;
    srcs[1] = (const char*)g_efrag + 8192; szs[1] = 8192;
    #pragma unroll
    for (int l = 0; l < 3; l++)
        #pragma unroll
        for (int p = 0; p < 4; p++) {
            srcs[2 + l * 4 + p] = (const char*)g_wfrag + l * 98304 + p * 24576;
            szs[2 + l * 4 + p] = 24576;
        }

    // pre-stage phase 0 into buf 0
    for (int o = tid * 16; o < szs[0]; o += NTH * 16)
        cpasync16(sb + SO_W + o, srcs[0] + o);
    cpcommit(); cpwaitall();
    __syncthreads();

    int buf = 0;
    int ph = 0;                       // current phase index
    const u32 aoff = (u32)(warp * 2048 + lane * 16);

    #pragma unroll 1
    for (int t = 0; t < TSTEPS; t++) {

        // ================= embedding =================
        float aE[8][4];
        #pragma unroll
        for (int n = 0; n < 8; n++) { aE[n][0]=0.f; aE[n][1]=0.f; aE[n][2]=0.f; aE[n][3]=0.f; }

        #pragma unroll
        for (int p = 0; p < 2; p++) {
            // stage next phase
            {
                int nx = ph + 1;
                u32 wbn = sb + SO_W + (buf ^ 1) * 24576;
                for (int o = tid * 16; o < szs[nx]; o += NTH * 16)
                    cpasync16(wbn + o, srcs[nx] + o);
                cpcommit();
            }
            const u32 wb = sb + SO_W + buf * 24576;
            #pragma unroll 1
            for (int kt = 0; kt < 4; kt++) {
                u32 ah[4], al[4];
                lds128(ah, sb + 3 * 32768 + (u32)(kt * 512) + aoff);
                if (p == 0) lds128(al, sb + 3 * 32768 + 16384 + (u32)(kt * 512) + aoff);
                #pragma unroll
                for (int nt = 0; nt < 8; nt++) {
                    u32 b0, b1;
                    lds64(b0, b1, wb + (u32)(((kt * 8 + nt) * 32 + lane) * 8));
                    mma16816(aE[nt], ah, b0, b1);
                    if (p == 0) mma16816(aE[nt], al, b0, b1);
                }
            }
            cpwaitall(); __syncthreads(); buf ^= 1; ph++;
        }
        // emb epilogue -> X (state 0)
        #pragma unroll
        for (int nt = 0; nt < 8; nt++) {
            int c0 = nt * 8 + 2 * tg;
            float e0 = __ldg(emb_b + c0), e1 = __ldg(emb_b + c0 + 1);
            float x00 = aE[nt][0] + e0, x01 = aE[nt][1] + e1;
            float x10 = aE[nt][2] + e0, x11 = aE[nt][3] + e1;
            u32 hi0 = packbf(x00, x01), hi1 = packbf(x10, x11);
            u32 lo0 = packbf(x00 - blo(hi0), x01 - bhi(hi0));
            u32 lo1 = packbf(x10 - blo(hi1), x11 - bhi(hi1));
            u32 ad = sb + (u32)((nt >> 1) * 512 + (nt & 1) * 8) + aoff;
            sts64(ad, hi0, hi1);
            sts64(ad + 16384, lo0, lo1);
        }

        // ================= 3 GRU layers =================
        #pragma unroll 1
        for (int l = 0; l < 3; l++) {
            float aR[8][4], aZ[8][4], aN[8][4], aM[8][4];
            #pragma unroll
            for (int n = 0; n < 8; n++)
                #pragma unroll
                for (int j = 0; j < 4; j++) { aR[n][j]=0.f; aZ[n][j]=0.f; aN[n][j]=0.f; aM[n][j]=0.f; }

            #pragma unroll
            for (int p4 = 0; p4 < 4; p4++) {
                {
                    int nx = (ph + 1) % 14;
                    u32 wbn = sb + SO_W + (buf ^ 1) * 24576;
                    for (int o = tid * 16; o < szs[nx]; o += NTH * 16)
                        cpasync16(wbn + o, srcs[nx] + o);
                    cpcommit();
                }
                const u32 wb = sb + SO_W + buf * 24576;
                const int stA = (p4 < 2) ? l : (l + 1);   // x-source or h-source
                const bool useLo = (p4 & 1) == 0;
                const u32 abase = sb + (u32)(stA * 32768) + aoff;
                #pragma unroll 1
                for (int kt = 0; kt < 4; kt++) {
                    u32 ah[4], al[4];
                    lds128(ah, abase + (u32)(kt * 512));
                    if (useLo) lds128(al, abase + 16384 + (u32)(kt * 512));
                    u32 wrow = wb + (u32)((kt * 24 * 32 + lane) * 8);
                    #pragma unroll
                    for (int nt = 0; nt < 8; nt++) {
                        u32 b0, b1;
                        lds64(b0, b1, wrow + (u32)(nt * 256));
                        mma16816(aR[nt], ah, b0, b1);
                        if (useLo) mma16816(aR[nt], al, b0, b1);
                    }
                    #pragma unroll
                    for (int nt = 0; nt < 8; nt++) {
                        u32 b0, b1;
                        lds64(b0, b1, wrow + (u32)((8 + nt) * 256));
                        mma16816(aZ[nt], ah, b0, b1);
                        if (useLo) mma16816(aZ[nt], al, b0, b1);
                    }
                    #pragma unroll
                    for (int nt = 0; nt < 8; nt++) {
                        u32 b0, b1;
                        lds64(b0, b1, wrow + (u32)((16 + nt) * 256));
                        if (p4 < 2) {
                            mma16816(aN[nt], ah, b0, b1);
                            if (useLo) mma16816(aN[nt], al, b0, b1);
                        } else {
                            mma16816(aM[nt], ah, b0, b1);
                            if (useLo) mma16816(aM[nt], al, b0, b1);
                        }
                    }
                }
                cpwaitall(); __syncthreads(); buf ^= 1; ph = (ph + 1) % 14;
            }

            // ---- layer epilogue: gates, h update, (l==2) output ----
            const float* gb = g_bias + l * 256;
            const u32 hbase = sb + (u32)((l + 1) * 32768) + aoff;
            float oA0 = 0.f, oA1 = 0.f, oB0 = 0.f, oB1 = 0.f;
            #pragma unroll
            for (int nt = 0; nt < 8; nt++) {
                int c0 = nt * 8 + 2 * tg;
                float br0 = __ldg(gb + c0),        br1 = __ldg(gb + c0 + 1);
                float bz0 = __ldg(gb + 64 + c0),   bz1 = __ldg(gb + 64 + c0 + 1);
                float bn0 = __ldg(gb + 128 + c0),  bn1 = __ldg(gb + 128 + c0 + 1);
                float bm0 = __ldg(gb + 192 + c0),  bm1 = __ldg(gb + 192 + c0 + 1);
                u32 ad = hbase + (u32)((nt >> 1) * 512 + (nt & 1) * 8);
                u32 hh0, hh1, hl0, hl1;
                lds64(hh0, hh1, ad);
                lds64(hl0, hl1, ad + 16384);
                float ho00 = blo(hh0) + blo(hl0), ho01 = bhi(hh0) + bhi(hl0);
                float ho10 = blo(hh1) + blo(hl1), ho11 = bhi(hh1) + bhi(hl1);

                float r, z, n;
                r = sigmf(aR[nt][0] + br0); z = sigmf(aZ[nt][0] + bz0);
                n = tanhfast(aN[nt][0] + bn0 + r * (aM[nt][0] + bm0));
                float h00 = n + z * (ho00 - n);
                r = sigmf(aR[nt][1] + br1); z = sigmf(aZ[nt][1] + bz1);
                n = tanhfast(aN[nt][1] + bn1 + r * (aM[nt][1] + bm1));
                float h01 = n + z * (ho01 - n);
                r = sigmf(aR[nt][2] + br0); z = sigmf(aZ[nt][2] + bz0);
                n = tanhfast(aN[nt][2] + bn0 + r * (aM[nt][2] + bm0));
                float h10 = n + z * (ho10 - n);
                r = sigmf(aR[nt][3] + br1); z = sigmf(aZ[nt][3] + bz1);
                n = tanhfast(aN[nt][3] + bn1 + r * (aM[nt][3] + bm1));
                float h11 = n + z * (ho11 - n);

                u32 hi0 = packbf(h00, h01), hi1 = packbf(h10, h11);
                u32 lo0 = packbf(h00 - blo(hi0), h01 - bhi(hi0));
                u32 lo1 = packbf(h10 - blo(hi1), h11 - bhi(hi1));
                sts64(ad, hi0, hi1);
                sts64(ad + 16384, lo0, lo1);

                if (l == 2) {
                    float w00 = __ldg(out_w + c0),      w01 = __ldg(out_w + c0 + 1);
                    float w10 = __ldg(out_w + 64 + c0), w11 = __ldg(out_w + 64 + c0 + 1);
                    oA0 += h00 * w00 + h01 * w01;   // row g,  j=0
                    oA1 += h00 * w10 + h01 * w11;   // row g,  j=1
                    oB0 += h10 * w00 + h11 * w01;   // row g+8
                    oB1 += h10 * w10 + h11 * w11;
                }
            }
            if (l == 2) {
                #pragma unroll
                for (int m = 1; m <= 2; m <<= 1) {
                    oA0 += __shfl_xor_sync(0xffffffffu, oA0, m);
                    oA1 += __shfl_xor_sync(0xffffffffu, oA1, m);
                    oB0 += __shfl_xor_sync(0xffffffffu, oB0, m);
                    oB1 += __shfl_xor_sync(0xffffffffu, oB1, m);
                }
                if (tg == 0) {
                    size_t r = (size_t)(row0 + warp * 16 + g) * (TSTEPS * 2) + t * 2;
                    out[r]     = oA0 + __ldg(out_b);
                    out[r + 1] = oA1 + __ldg(out_b + 1);
                } else if (tg == 1) {
                    size_t r = (size_t)(row0 + warp * 16 + g + 8) * (TSTEPS * 2) + t * 2;
                    out[r]     = oB0 + __ldg(out_b);
                    out[r + 1] = oB1 + __ldg(out_b + 1);
                }
            }
        }
    }
}

extern "C" void kernel_launch(void* const* d_in, const int* in_sizes, int n_in,
                              void* d_out, int out_size)
{
    const float* enc   = (const float*)d_in[0];
    const float* emb_w = (const float*)d_in[1];
    const float* emb_b = (const float*)d_in[2];
    const float* w_ih  = (const float*)d_in[3];
    const float* w_hh  = (const float*)d_in[4];
    const float* b_ih  = (const float*)d_in[5];
    const float* b_hh  = (const float*)d_in[6];
    const float* out_w = (const float*)d_in[7];
    const float* out_b = (const float*)d_in[8];

    cudaFuncSetAttribute(gru_mma_kernel,
                         cudaFuncAttributeMaxDynamicSharedMemorySize, SMEMSZ);

    prep_kernel<<<96, 256>>>(emb_w, w_ih, w_hh, b_ih, b_hh);
    gru_mma_kernel<<<128, NTH, SMEMSZ>>>(enc, emb_b, out_w, out_b, (float*)d_out);
}

// round 8
// speedup vs baseline: 2.5044x; 1.1006x over previous
#include <cuda_runtime.h>
#include <cuda_bf16.h>

typedef unsigned long long u64;
typedef unsigned int u32;

#define TSTEPS 128
#define NTH    512

// =============== prepped weights (global scratch) ===============
// g_wfrag layout [l][side][part][kt(4)][nt(24)][lane(32)][reg(2)] u32
//   side0=w_ih side1=w_hh ; part0=hi part1=lo(residual)
__device__ __align__(16) u32 g_wfrag[3 * 2 * 2 * 4 * 24 * 32 * 2];   // 73728 u32
// emb: [part][kt(4)][nt(8)][lane][reg] u32
__device__ __align__(16) u32 g_efrag[2 * 4 * 8 * 32 * 2];            // 4096 u32
// combined biases: per layer [0:64)=bir+bhr [64:128)=biz+bhz [128:192)=bin [192:256)=bhn
__device__ __align__(16) float g_bias[3 * 256];

__device__ __forceinline__ u32 packbf(float a, float b) {
    return (u32)__bfloat16_as_ushort(__float2bfloat16(a)) |
           ((u32)__bfloat16_as_ushort(__float2bfloat16(b)) << 16);
}
__device__ __forceinline__ float blo(u32 v) {
    return __bfloat162float(__ushort_as_bfloat16((unsigned short)(v & 0xFFFF)));
}
__device__ __forceinline__ float bhi(u32 v) {
    return __bfloat162float(__ushort_as_bfloat16((unsigned short)(v >> 16)));
}

__global__ void prep_kernel(const float* __restrict__ emb_w,
                            const float* __restrict__ w_ih,
                            const float* __restrict__ w_hh,
                            const float* __restrict__ b_ih,
                            const float* __restrict__ b_hh)
{
    int i0 = blockIdx.x * blockDim.x + threadIdx.x;
    int st = gridDim.x * blockDim.x;
    for (int i = i0; i < 73728; i += st) {
        int reg  = i & 1;
        int lane = (i >> 1) & 31;
        int nt   = (i >> 6) % 24;
        int kt   = (i / 1536) % 4;
        int part = (i / 6144) % 2;
        int side = (i / 12288) % 2;
        int l    = i / 24576;
        int g = lane >> 2, tg = lane & 3;
        int n = nt * 8 + g;
        int k0 = kt * 16 + tg * 2 + reg * 8;
        const float* W = side ? w_hh : w_ih;
        float w0 = W[(l * 192 + n) * 64 + k0];
        float w1 = W[(l * 192 + n) * 64 + k0 + 1];
        if (part == 0) {
            g_wfrag[i] = packbf(w0, w1);
        } else {
            float r0 = w0 - __bfloat162float(__float2bfloat16(w0));
            float r1 = w1 - __bfloat162float(__float2bfloat16(w1));
            g_wfrag[i] = packbf(r0, r1);
        }
    }
    for (int i = i0; i < 4096; i += st) {
        int reg  = i & 1;
        int lane = (i >> 1) & 31;
        int nt   = (i >> 6) & 7;
        int kt   = (i >> 9) & 3;
        int part = i >> 11;
        int g = lane >> 2, tg = lane & 3;
        int n = nt * 8 + g;
        int k0 = kt * 16 + tg * 2 + reg * 8;
        float w0 = emb_w[n * 64 + k0], w1 = emb_w[n * 64 + k0 + 1];
        if (part == 0) {
            g_efrag[i] = packbf(w0, w1);
        } else {
            float r0 = w0 - __bfloat162float(__float2bfloat16(w0));
            float r1 = w1 - __bfloat162float(__float2bfloat16(w1));
            g_efrag[i] = packbf(r0, r1);
        }
    }
    for (int i = i0; i < 3 * 64; i += st) {
        int l = i >> 6, c = i & 63;
        g_bias[l * 256 + c]       = b_ih[l * 192 + c]      + b_hh[l * 192 + c];
        g_bias[l * 256 + 64 + c]  = b_ih[l * 192 + 64 + c] + b_hh[l * 192 + 64 + c];
        g_bias[l * 256 + 128 + c] = b_ih[l * 192 + 128 + c];
        g_bias[l * 256 + 192 + c] = b_hh[l * 192 + 128 + c];
    }
}

// =============== device helpers ===============
__device__ __forceinline__ u32 smem_u32(const void* p) {
    u32 a;
    asm("{ .reg .u64 t; cvta.to.shared.u64 t, %1; cvt.u32.u64 %0, t; }" : "=r"(a) : "l"(p));
    return a;
}
__device__ __forceinline__ void mma16816(float* d, const u32* a, u32 b0, u32 b1) {
    asm volatile(
        "mma.sync.aligned.m16n8k16.row.col.f32.bf16.bf16.f32 "
        "{%0,%1,%2,%3},{%4,%5,%6,%7},{%8,%9},{%0,%1,%2,%3};"
        : "+f"(d[0]), "+f"(d[1]), "+f"(d[2]), "+f"(d[3])
        : "r"(a[0]), "r"(a[1]), "r"(a[2]), "r"(a[3]), "r"(b0), "r"(b1));
}
__device__ __forceinline__ void lds128(u32* r, u32 a) {
    asm volatile("ld.shared.v4.u32 {%0,%1,%2,%3},[%4];"
                 : "=r"(r[0]), "=r"(r[1]), "=r"(r[2]), "=r"(r[3]) : "r"(a));
}
__device__ __forceinline__ void lds64(u32& x, u32& y, u32 a) {
    asm volatile("ld.shared.v2.u32 {%0,%1},[%2];" : "=r"(x), "=r"(y) : "r"(a));
}
__device__ __forceinline__ void sts64(u32 a, u32 x, u32 y) {
    asm volatile("st.shared.v2.u32 [%0],{%1,%2};" :: "r"(a), "r"(x), "r"(y));
}
__device__ __forceinline__ void cpasync16(u32 s, const void* g) {
    asm volatile("cp.async.ca.shared.global [%0],[%1],16;" :: "r"(s), "l"(g));
}
__device__ __forceinline__ void cpcommit() { asm volatile("cp.async.commit_group;"); }
__device__ __forceinline__ void cpwaitall() { asm volatile("cp.async.wait_group 0;"); }
__device__ __forceinline__ float sigmf(float x) { return __fdividef(1.f, 1.f + __expf(-x)); }
__device__ __forceinline__ float tanhfast(float x) { return 1.f - __fdividef(2.f, __expf(2.f * x) + 1.f); }

// SMEM layout (bytes):
//   states 0..3 at s*32768 (hi at +0, lo at +16384)             = 131072
//   output partials at SO_P (8 mt x 2 half x 16 row x 2 j f32)  = 2048
//   weight double-buffer at SO_W: 2 x 49152
#define SO_P   131072
#define SO_W   133120
#define WBUF   49152
#define SMEMSZ (SO_W + 2 * WBUF)   /* 231424 */

extern "C" __global__ void __launch_bounds__(NTH, 1)
gru_mma_kernel(const float* __restrict__ enc,
               const float* __restrict__ emb_b,
               const float* __restrict__ out_w,
               const float* __restrict__ out_b,
               float* __restrict__ out)
{
    extern __shared__ char smc[];
    const u32 sb   = smem_u32(smc);
    const int tid  = threadIdx.x;
    const int lane = tid & 31;
    const int warp = tid >> 5;            // 16 warps
    const int mt   = warp >> 1;           // 8 mtiles x 16 rows
    const int half = warp & 1;            // column half (32 cols)
    const int g    = lane >> 2;
    const int tg   = lane & 3;
    const int row0 = blockIdx.x * 128;

    // ---- init H0/H1/H2 (states 1..3) frag-linear from enc ----
    for (int i = tid; i < 128 * 32; i += NTH) {
        int m = i >> 5, kp = i & 31;
        int k = kp * 2;
        float v0 = enc[(size_t)(row0 + m) * 64 + k];
        float v1 = enc[(size_t)(row0 + m) * 64 + k + 1];
        u32 hi = packbf(v0, v1);
        u32 lo = packbf(v0 - blo(hi), v1 - bhi(hi));
        int kt = k >> 4, kin = k & 15;
        int gg = m & 15;
        int reg = ((kin >= 8) ? 2 : 0) + ((gg >= 8) ? 1 : 0);
        int ln = (gg & 7) * 4 + ((kin & 7) >> 1);
        u32 off = (u32)((m >> 4) * 2048 + kt * 512 + ln * 16 + reg * 4);
        #pragma unroll
        for (int s = 1; s <= 3; s++) {
            *(u32*)(smc + s * 32768 + off)         = hi;
            *(u32*)(smc + s * 32768 + 16384 + off) = lo;
        }
    }

    // phases: 0 = emb(hi+lo, 16KB); 1+2l+s = layer l side s (hi+lo, 48KB)
    const char* srcs[7]; int szs[7];
    srcs[0] = (const char*)g_efrag; szs[0] = 16384;
    #pragma unroll
    for (int l = 0; l < 3; l++)
        #pragma unroll
        for (int s = 0; s < 2; s++) {
            srcs[1 + 2 * l + s] = (const char*)g_wfrag + l * 98304 + s * 49152;
            szs[1 + 2 * l + s] = 49152;
        }

    // pre-stage phase 0 into buf 0
    for (int o = tid * 16; o < szs[0]; o += NTH * 16)
        cpasync16(sb + SO_W + o, srcs[0] + o);
    cpcommit(); cpwaitall();
    __syncthreads();

    int buf = 0;
    int ph = 0;
    const u32 aoff = (u32)(mt * 2048 + lane * 16);
    float* sp = (float*)(smc + SO_P);

    #pragma unroll 1
    for (int t = 0; t < TSTEPS; t++) {

        // ================= phase 0: embedding =================
        float aE[4][4];
        #pragma unroll
        for (int j = 0; j < 4; j++) { aE[j][0]=0.f; aE[j][1]=0.f; aE[j][2]=0.f; aE[j][3]=0.f; }
        {
            u32 wbn = sb + SO_W + (buf ^ 1) * WBUF;
            for (int o = tid * 16; o < szs[1]; o += NTH * 16)
                cpasync16(wbn + o, srcs[1] + o);
            cpcommit();
        }
        {
            const u32 wb = sb + SO_W + buf * WBUF;
            const u32 abase = sb + 3 * 32768 + aoff;
            #pragma unroll 1
            for (int kt = 0; kt < 4; kt++) {
                u32 ah[4], al[4];
                lds128(ah, abase + (u32)(kt * 512));
                lds128(al, abase + 16384 + (u32)(kt * 512));
                #pragma unroll
                for (int j = 0; j < 4; j++) {
                    int nt = half * 4 + j;
                    u32 ba = wb + (u32)(((kt * 8 + nt) * 32 + lane) * 8);
                    u32 b0, b1;
                    lds64(b0, b1, ba);
                    mma16816(aE[j], ah, b0, b1);
                    mma16816(aE[j], al, b0, b1);
                    lds64(b0, b1, ba + 8192);
                    mma16816(aE[j], ah, b0, b1);
                }
            }
        }
        cpwaitall(); __syncthreads(); buf ^= 1; ph = 1;

        // emb epilogue -> X (state 0), own 32 cols
        #pragma unroll
        for (int j = 0; j < 4; j++) {
            int ntc = half * 4 + j;
            int c0 = ntc * 8 + 2 * tg;
            float e0 = __ldg(emb_b + c0), e1 = __ldg(emb_b + c0 + 1);
            float x00 = aE[j][0] + e0, x01 = aE[j][1] + e1;
            float x10 = aE[j][2] + e0, x11 = aE[j][3] + e1;
            u32 hi0 = packbf(x00, x01), hi1 = packbf(x10, x11);
            u32 lo0 = packbf(x00 - blo(hi0), x01 - bhi(hi0));
            u32 lo1 = packbf(x10 - blo(hi1), x11 - bhi(hi1));
            u32 ad = sb + (u32)((ntc >> 1) * 512 + (ntc & 1) * 8) + aoff;
            sts64(ad, hi0, hi1);
            sts64(ad + 16384, lo0, lo1);
        }
        __syncthreads();   // X complete (written by both halves) before layer-0 MMAs

        // ================= 3 GRU layers =================
        #pragma unroll 1
        for (int l = 0; l < 3; l++) {
            float aR[4][4], aZ[4][4], aN[4][4], aM[4][4];
            #pragma unroll
            for (int j = 0; j < 4; j++)
                #pragma unroll
                for (int q = 0; q < 4; q++) { aR[j][q]=0.f; aZ[j][q]=0.f; aN[j][q]=0.f; aM[j][q]=0.f; }

            #pragma unroll
            for (int ws = 0; ws < 2; ws++) {        // 0 = x*Wi, 1 = h*Wh
                {
                    int nx = (ph + 1) % 7;
                    u32 wbn = sb + SO_W + (buf ^ 1) * WBUF;
                    for (int o = tid * 16; o < szs[nx]; o += NTH * 16)
                        cpasync16(wbn + o, srcs[nx] + o);
                    cpcommit();
                }
                const u32 wb = sb + SO_W + buf * WBUF;
                const int stA = (ws == 0) ? l : (l + 1);
                const u32 abase = sb + (u32)(stA * 32768) + aoff;
                #pragma unroll 1
                for (int kt = 0; kt < 4; kt++) {
                    u32 ah[4], al[4];
                    lds128(ah, abase + (u32)(kt * 512));
                    lds128(al, abase + 16384 + (u32)(kt * 512));
                    #pragma unroll
                    for (int gate = 0; gate < 3; gate++) {
                        float (*acc)[4] = (gate == 0) ? aR :
                                          (gate == 1) ? aZ :
                                          ((ws == 0) ? aN : aM);
                        #pragma unroll
                        for (int j = 0; j < 4; j++) {
                            int nt = gate * 8 + half * 4 + j;
                            u32 ba = wb + (u32)(((kt * 24 + nt) * 32 + lane) * 8);
                            u32 b0, b1;
                            lds64(b0, b1, ba);
                            mma16816(acc[j], ah, b0, b1);
                            mma16816(acc[j], al, b0, b1);
                            lds64(b0, b1, ba + 24576);
                            mma16816(acc[j], ah, b0, b1);
                        }
                    }
                }
                cpwaitall(); __syncthreads(); buf ^= 1; ph = (ph + 1) % 7;
            }

            // ---- layer epilogue: gates, h update, (l==2) output partials ----
            const float* gb = g_bias + l * 256;
            const u32 hbase = sb + (u32)((l + 1) * 32768) + aoff;
            float oA0 = 0.f, oA1 = 0.f, oB0 = 0.f, oB1 = 0.f;
            #pragma unroll
            for (int j = 0; j < 4; j++) {
                int ntc = half * 4 + j;
                int c0 = ntc * 8 + 2 * tg;
                float br0 = __ldg(gb + c0),        br1 = __ldg(gb + c0 + 1);
                float bz0 = __ldg(gb + 64 + c0),   bz1 = __ldg(gb + 64 + c0 + 1);
                float bn0 = __ldg(gb + 128 + c0),  bn1 = __ldg(gb + 128 + c0 + 1);
                float bm0 = __ldg(gb + 192 + c0),  bm1 = __ldg(gb + 192 + c0 + 1);
                u32 ad = hbase + (u32)((ntc >> 1) * 512 + (ntc & 1) * 8);
                u32 hh0, hh1, hl0, hl1;
                lds64(hh0, hh1, ad);
                lds64(hl0, hl1, ad + 16384);
                float ho00 = blo(hh0) + blo(hl0), ho01 = bhi(hh0) + bhi(hl0);
                float ho10 = blo(hh1) + blo(hl1), ho11 = bhi(hh1) + bhi(hl1);

                float r, z, n;
                r = sigmf(aR[j][0] + br0); z = sigmf(aZ[j][0] + bz0);
                n = tanhfast(aN[j][0] + bn0 + r * (aM[j][0] + bm0));
                float h00 = n + z * (ho00 - n);
                r = sigmf(aR[j][1] + br1); z = sigmf(aZ[j][1] + bz1);
                n = tanhfast(aN[j][1] + bn1 + r * (aM[j][1] + bm1));
                float h01 = n + z * (ho01 - n);
                r = sigmf(aR[j][2] + br0); z = sigmf(aZ[j][2] + bz0);
                n = tanhfast(aN[j][2] + bn0 + r * (aM[j][2] + bm0));
                float h10 = n + z * (ho10 - n);
                r = sigmf(aR[j][3] + br1); z = sigmf(aZ[j][3] + bz1);
                n = tanhfast(aN[j][3] + bn1 + r * (aM[j][3] + bm1));
                float h11 = n + z * (ho11 - n);

                u32 hi0 = packbf(h00, h01), hi1 = packbf(h10, h11);
                u32 lo0 = packbf(h00 - blo(hi0), h01 - bhi(hi0));
                u32 lo1 = packbf(h10 - blo(hi1), h11 - bhi(hi1));
                sts64(ad, hi0, hi1);
                sts64(ad + 16384, lo0, lo1);

                if (l == 2) {
                    float w00 = __ldg(out_w + c0),      w01 = __ldg(out_w + c0 + 1);
                    float w10 = __ldg(out_w + 64 + c0), w11 = __ldg(out_w + 64 + c0 + 1);
                    oA0 += h00 * w00 + h01 * w01;
                    oA1 += h00 * w10 + h01 * w11;
                    oB0 += h10 * w00 + h11 * w01;
                    oB1 += h10 * w10 + h11 * w11;
                }
            }
            if (l == 2) {
                #pragma unroll
                for (int m = 1; m <= 2; m <<= 1) {
                    oA0 += __shfl_xor_sync(0xffffffffu, oA0, m);
                    oA1 += __shfl_xor_sync(0xffffffffu, oA1, m);
                    oB0 += __shfl_xor_sync(0xffffffffu, oB0, m);
                    oB1 += __shfl_xor_sync(0xffffffffu, oB1, m);
                }
                if (tg == 0) {
                    int base = ((mt * 2 + half) * 16 + g) * 2;
                    sp[base]     = oA0;
                    sp[base + 1] = oA1;
                    int base2 = ((mt * 2 + half) * 16 + g + 8) * 2;
                    sp[base2]     = oB0;
                    sp[base2 + 1] = oB1;
                }
            }
            __syncthreads();   // h_l complete before layer l+1 (or next-t emb / out combine)

            if (l == 2 && half == 0) {
                int row = lane >> 1, j = lane & 1;
                float v = sp[((mt * 2) * 16 + row) * 2 + j] +
                          sp[((mt * 2 + 1) * 16 + row) * 2 + j] + __ldg(out_b + j);
                out[(size_t)(row0 + mt * 16 + row) * (TSTEPS * 2) + t * 2 + j] = v;
            }
        }
    }
}

extern "C" void kernel_launch(void* const* d_in, const int* in_sizes, int n_in,
                              void* d_out, int out_size)
{
    const float* enc   = (const float*)d_in[0];
    const float* emb_w = (const float*)d_in[1];
    const float* emb_b = (const float*)d_in[2];
    const float* w_ih  = (const float*)d_in[3];
    const float* w_hh  = (const float*)d_in[4];
    const float* b_ih  = (const float*)d_in[5];
    const float* b_hh  = (const float*)d_in[6];
    const float* out_w = (const float*)d_in[7];
    const float* out_b = (const float*)d_in[8];

    cudaFuncSetAttribute(gru_mma_kernel,
                         cudaFuncAttributeMaxDynamicSharedMemorySize, SMEMSZ);

    prep_kernel<<<96, 256>>>(emb_w, w_ih, w_hh, b_ih, b_hh);
    gru_mma_kernel<<<128, NTH, SMEMSZ>>>(enc, emb_b, out_w, out_b, (float*)d_out);
}